// round 13
// baseline (speedup 1.0000x reference)
#include <cuda_runtime.h>
#include <cstdint>

// Problem dims (fixed by reference)
#define BB 256
#define TT 1024
#define DD 64
#define HH 128
#define NB 8      // batches per scan CTA (MMA N dimension)

typedef unsigned long long ull;

static constexpr size_t BT  = (size_t)BB * TT;        // 262144
static constexpr size_t BTH = (size_t)BB * TT * HH;   // 33554432

// Interleaved scratch: (gate_x_K, tanh(gate_x_z)) per (b,t,h). No cudaMalloc.
// Padded 4 rows so the scan prefetch (distance 2) is unconditional.
__device__ float2 g_gz[BTH + 4 * HH];

// ---- packed f32x2 helpers (proj kernel) ----
__device__ __forceinline__ void fma2(ull& acc, ull a, ull b) {
    asm("fma.rn.f32x2 %0, %1, %2, %0;" : "+l"(acc) : "l"(a), "l"(b));
}
__device__ __forceinline__ void add2(ull& a, ull b) {
    asm("add.rn.f32x2 %0, %0, %1;" : "+l"(a) : "l"(b));
}
__device__ __forceinline__ float2 unpk(ull v) {
    float2 f;
    asm("mov.b64 {%0, %1}, %2;" : "=f"(f.x), "=f"(f.y) : "l"(v));
    return f;
}
// Hardware tanh (MUFU.TANH)
__device__ __forceinline__ float tanh_hw(float x) {
    float r;
    asm("tanh.approx.f32 %0, %1;" : "=f"(r) : "f"(x));
    return r;
}
__device__ __forceinline__ float sigmoid_hw(float x) {
    return fmaf(0.5f, tanh_hw(0.5f * x), 0.5f);
}
// Round f32 -> tf32 (low 13 mantissa bits zeroed), returned as f32 bits.
__device__ __forceinline__ uint32_t to_tf32(float x) {
    uint32_t u;
    asm("cvt.rn.tf32.f32 %0, %1;" : "=r"(u) : "f"(x));
    return u;
}

// ---------------------------------------------------------------------------
// Kernel 1: input projections (unchanged; ~225us)
// ---------------------------------------------------------------------------
__global__ void __launch_bounds__(128)
proj_kernel(const float* __restrict__ x,
            const float* __restrict__ WxK, const float* __restrict__ bxK,
            const float* __restrict__ Wxz, const float* __restrict__ bxz)
{
    constexpr int ROWS = 64;
    __shared__ __align__(16) float xs[ROWS * DD];   // 16 KB

    const int i = threadIdx.x;
    const size_t row0 = (size_t)blockIdx.x * ROWS;

    const float4* xg  = (const float4*)(x + row0 * DD);
    float4*       xs4 = (float4*)xs;
#pragma unroll
    for (int k = 0; k < 8; k++) xs4[i + 128 * k] = xg[i + 128 * k];

    ulonglong2 wK[16], wz[16];
    {
        const ulonglong2* wKr = (const ulonglong2*)(WxK + i * DD);
        const ulonglong2* wzr = (const ulonglong2*)(Wxz + i * DD);
#pragma unroll
        for (int m = 0; m < 16; m++) { wK[m] = wKr[m]; wz[m] = wzr[m]; }
    }
    const float bK = bxK[i];
    const float bz = bxz[i];
    __syncthreads();

    for (int r = 0; r < ROWS; r += 2) {
        const ulonglong2* xr0 = (const ulonglong2*)(xs + r * DD);
        const ulonglong2* xr1 = (const ulonglong2*)(xs + (r + 1) * DD);
        ull aK0 = 0, aK1 = 0, az0 = 0, az1 = 0;
        ull cK0 = 0, cK1 = 0, cz0 = 0, cz1 = 0;
#pragma unroll
        for (int m = 0; m < 16; m++) {
            ulonglong2 xv0 = xr0[m];
            ulonglong2 xv1 = xr1[m];
            fma2(aK0, wK[m].x, xv0.x); fma2(aK1, wK[m].y, xv0.y);
            fma2(az0, wz[m].x, xv0.x); fma2(az1, wz[m].y, xv0.y);
            fma2(cK0, wK[m].x, xv1.x); fma2(cK1, wK[m].y, xv1.y);
            fma2(cz0, wz[m].x, xv1.x); fma2(cz1, wz[m].y, xv1.y);
        }
        add2(aK0, aK1); add2(az0, az1); add2(cK0, cK1); add2(cz0, cz1);
        float2 k0 = unpk(aK0), z0 = unpk(az0);
        float2 k1 = unpk(cK0), z1 = unpk(cz0);

        size_t n0 = (row0 + r) * HH + i;
        size_t n1 = n0 + HH;
        g_gz[n0] = make_float2(k0.x + k0.y + bK, tanh_hw(z0.x + z0.y + bz));
        g_gz[n1] = make_float2(k1.x + k1.y + bK, tanh_hw(z1.x + z1.y + bz));
    }
}

// ---------------------------------------------------------------------------
// Kernel 2: tensor-core scan (r12 math, restructured inner loop).
// One CTA (256 thr = 8 warps) handles NB=8 batches; grid = 32.
// Per step: C[128x8] = W[128x128] @ H[128x8] via mma.m16n8k8.tf32, A
// (weights) register-resident across ALL 1024 steps.
// Round-12 fix: ALL 32 B words are prefetched into registers before the MMA
// chain (conflict-free distinct-address LDS.32 -> latency paid once, not
// 16x serially), and C uses 8 independent accumulator chains (depth 2).
//
// Fragment maps (g = lane>>2, tig = lane&3):
//   A: a0=(g,tig) a1=(g+8,tig) a2=(g,tig+4) a3=(g+8,tig+4)   [row-major]
//   B: b0=(k=tig, n=g) b1=(k=tig+4, n=g)                      [col-major]
//   C: c0=(g,2tig) c1=(g,2tig+1) c2=(g+8,2tig) c3=(g+8,2tig+1)
// ---------------------------------------------------------------------------
__device__ __forceinline__ void mma_tf32(float c[4], const uint32_t a[4],
                                         uint32_t b0, uint32_t b1) {
    asm volatile(
        "mma.sync.aligned.m16n8k8.row.col.f32.tf32.tf32.f32 "
        "{%0,%1,%2,%3}, {%4,%5,%6,%7}, {%8,%9}, {%0,%1,%2,%3};"
        : "+f"(c[0]), "+f"(c[1]), "+f"(c[2]), "+f"(c[3])
        : "r"(a[0]), "r"(a[1]), "r"(a[2]), "r"(a[3]), "r"(b0), "r"(b1));
}

__global__ void __launch_bounds__(256, 1)
scan_kernel(const float* __restrict__ WhK, const float* __restrict__ bhK,
            float* __restrict__ out, int dup)
{
    // [buf][n][k] with 132-float rows: bank(n*132+k) = (4n+k)%32 ->
    // B loads and h stores are conflict-free.
    __shared__ float hs[2][NB][132];

    const int tid  = threadIdx.x;
    const int w    = tid >> 5;
    const int lane = tid & 31;
    const int g    = lane >> 2;
    const int tig  = lane & 3;
    const int b0blk = blockIdx.x * NB;

    // A fragments: W rows (16w+g, 16w+g+8), all 16 k-chunks, tf32.
    uint32_t A[16][4];
    const int i0 = 16 * w + g;
    const int i1 = i0 + 8;
#pragma unroll
    for (int kc = 0; kc < 16; kc++) {
        int kb = 8 * kc + tig;
        A[kc][0] = to_tf32(WhK[i0 * HH + kb]);
        A[kc][1] = to_tf32(WhK[i1 * HH + kb]);
        A[kc][2] = to_tf32(WhK[i0 * HH + kb + 4]);
        A[kc][3] = to_tf32(WhK[i1 * HH + kb + 4]);
    }
    const float bh0 = bhK[i0];
    const float bh1 = bhK[i1];

    // This thread's 4 C elements: (i0,n0),(i0,n1),(i1,n0),(i1,n1)
    const int n0 = 2 * tig, n1 = n0 + 1;
    const int ii[4] = { i0, i0, i1, i1 };
    const int nn[4] = { n0, n1, n0, n1 };

    const float2* gp[4];
    float* op[4];
    float* oq[4];
    float h[4];
    float2 gza[4], gzb[4];
#pragma unroll
    for (int j = 0; j < 4; j++) {
        size_t base = ((size_t)(b0blk + nn[j]) * TT) * HH + ii[j];
        gp[j] = g_gz + base;
        op[j] = out + base;
        oq[j] = op[j] + BTH;
        h[j] = 0.0f;
        gza[j] = gp[j][0];
        gzb[j] = gp[j][HH];
        gp[j] += 2 * HH;
    }

    // zero stage buffer 0
    for (int idx = tid; idx < NB * 132; idx += 256)
        (&hs[0][0][0])[idx] = 0.0f;
    __syncthreads();

    int cur = 0;
    for (int t = 0; t < TT; t++) {
        const float* hb = &hs[cur][0][0] + g * 132 + tig;

        // ---- prefetch ALL B fragments (32 conflict-free LDS.32) ----
        uint32_t B0[16], B1[16];
#pragma unroll
        for (int kc = 0; kc < 16; kc++) {
            B0[kc] = __float_as_uint(hb[8 * kc]);
            B1[kc] = __float_as_uint(hb[8 * kc + 4]);
        }

        // ---- 16 MMAs into 8 independent accumulator chains (depth 2) ----
        float c[8][4];
#pragma unroll
        for (int ch = 0; ch < 8; ch++)
#pragma unroll
            for (int j = 0; j < 4; j++) c[ch][j] = 0.0f;
#pragma unroll
        for (int kc = 0; kc < 16; kc++)
            mma_tf32(c[kc & 7], A[kc], B0[kc], B1[kc]);

        // ---- reduce 8 chains ----
        float sj[4];
#pragma unroll
        for (int j = 0; j < 4; j++) {
            float s = ((c[0][j] + c[1][j]) + (c[2][j] + c[3][j]))
                    + ((c[4][j] + c[5][j]) + (c[6][j] + c[7][j]));
            sj[j] = s + ((j < 2) ? bh0 : bh1);
        }

        // ---- activation + output (4 (i,n) elements per thread) ----
#pragma unroll
        for (int j = 0; j < 4; j++) {
            float kg = sigmoid_hw(gza[j].x + sj[j]);
            h[j] = tanh_hw(fmaf(kg, gza[j].y - h[j], h[j]));
            gza[j] = gzb[j];
            gzb[j] = *gp[j];           // unconditional: scratch padded
            gp[j] += HH;
            op[j][0] = h[j];
            if (dup) oq[j][0] = h[j];
            op[j] += HH; oq[j] += HH;
        }

        // store tf32-rounded h for next step's B operand (conflict-free)
        int nxt = cur ^ 1;
        hs[nxt][n0][i0] = __uint_as_float(to_tf32(h[0]));
        hs[nxt][n1][i0] = __uint_as_float(to_tf32(h[1]));
        hs[nxt][n0][i1] = __uint_as_float(to_tf32(h[2]));
        hs[nxt][n1][i1] = __uint_as_float(to_tf32(h[3]));
        __syncthreads();
        cur = nxt;
    }
}

// ---------------------------------------------------------------------------
extern "C" void kernel_launch(void* const* d_in, const int* in_sizes, int n_in,
                              void* d_out, int out_size)
{
    const float* x   = (const float*)d_in[0];
    const float* WxK = (const float*)d_in[1];
    const float* bxK = (const float*)d_in[2];
    const float* Wxz = (const float*)d_in[3];
    const float* bxz = (const float*)d_in[4];
    const float* WhK = (const float*)d_in[5];
    const float* bhK = (const float*)d_in[6];
    float* out = (float*)d_out;

    proj_kernel<<<(int)(BT / 64), 128>>>(x, WxK, bxK, Wxz, bxz);

    const int dup = ((size_t)out_size >= 2 * BTH) ? 1 : 0;
    scan_kernel<<<BB / NB, 256>>>(WhK, bhK, out, dup);
}

// round 14
// speedup vs baseline: 2.0718x; 2.0718x over previous
#include <cuda_runtime.h>
#include <cstdint>

// Problem dims (fixed by reference)
#define BB 256
#define TT 1024
#define DD 64
#define HH 128
#define GRP 2   // batches per scan CTA (separate thread groups + named barriers)

typedef unsigned long long ull;

static constexpr size_t BT  = (size_t)BB * TT;        // 262144
static constexpr size_t BTH = (size_t)BB * TT * HH;   // 33554432

// Interleaved scratch: (gate_x_K, tanh(gate_x_z)) per (b,t,h). No cudaMalloc.
// Padded 4 rows so the scan prefetch (distance 3) is unconditional.
__device__ float2 g_gz[BTH + 4 * HH];

// ---- packed f32x2 helpers (scan kernel) ----
__device__ __forceinline__ void fma2(ull& acc, ull a, ull b) {
    asm("fma.rn.f32x2 %0, %1, %2, %0;" : "+l"(acc) : "l"(a), "l"(b));
}
__device__ __forceinline__ void add2(ull& a, ull b) {
    asm("add.rn.f32x2 %0, %0, %1;" : "+l"(a) : "l"(b));
}
__device__ __forceinline__ float2 unpk(ull v) {
    float2 f;
    asm("mov.b64 {%0, %1}, %2;" : "=f"(f.x), "=f"(f.y) : "l"(v));
    return f;
}
// Hardware tanh (MUFU.TANH)
__device__ __forceinline__ float tanh_hw(float x) {
    float r;
    asm("tanh.approx.f32 %0, %1;" : "=f"(r) : "f"(x));
    return r;
}
__device__ __forceinline__ float sigmoid_hw(float x) {
    return fmaf(0.5f, tanh_hw(0.5f * x), 0.5f);
}
// Round f32 -> tf32 (rn), returned as f32 bit pattern.
__device__ __forceinline__ uint32_t to_tf32(float x) {
    uint32_t u;
    asm("cvt.rn.tf32.f32 %0, %1;" : "=r"(u) : "f"(x));
    return u;
}

// m16n8k8 tf32 MMA. Fragment maps (g = lane>>2, tig = lane&3):
//   A (row-major): a0=(g,tig) a1=(g+8,tig) a2=(g,tig+4) a3=(g+8,tig+4)
//   B (col-major): b0=(k=tig, n=g) b1=(k=tig+4, n=g)
//   C: c0=(g,2tig) c1=(g,2tig+1) c2=(g+8,2tig) c3=(g+8,2tig+1)
__device__ __forceinline__ void mma_tf32(float c[4], const uint32_t a[4],
                                         uint32_t b0, uint32_t b1) {
    asm volatile(
        "mma.sync.aligned.m16n8k8.row.col.f32.tf32.tf32.f32 "
        "{%0,%1,%2,%3}, {%4,%5,%6,%7}, {%8,%9}, {%0,%1,%2,%3};"
        : "+f"(c[0]), "+f"(c[1]), "+f"(c[2]), "+f"(c[3])
        : "r"(a[0]), "r"(a[1]), "r"(a[2]), "r"(a[3]), "r"(b0), "r"(b1));
}

// ---------------------------------------------------------------------------
// Kernel 1: tensor-core input projections.
// C[BT x 256] = X[BT x 64] @ [WxK; Wxz]^T, output packed as float2 (gK, tanh(gz)).
// Per CTA: 64 x-rows, 128 threads (4 warps, warp w = m-tile rows 16w..16w+15).
// W staged once in smem (tf32-rounded, row stride 68 -> conflict-free LDS).
// 16 n-iterations; iter nt computes h-columns [8nt, 8nt+8) for BOTH gates.
// Dynamic smem: xs 64x68 | wks 128x68 | wzs 128x68 | bk 128 | bz 128.
// ---------------------------------------------------------------------------
#define XS_OFF  0
#define WK_OFF  (64 * 68)
#define WZ_OFF  (WK_OFF + 128 * 68)
#define BK_OFF  (WZ_OFF + 128 * 68)
#define BZ_OFF  (BK_OFF + 128)
#define PROJ_SMEM_FLOATS (BZ_OFF + 128)

__global__ void __launch_bounds__(128, 2)
proj_kernel(const float* __restrict__ x,
            const float* __restrict__ WxK, const float* __restrict__ bxK,
            const float* __restrict__ Wxz, const float* __restrict__ bxz)
{
    extern __shared__ float sm[];
    float* xs  = sm + XS_OFF;
    float* wks = sm + WK_OFF;
    float* wzs = sm + WZ_OFF;
    float* bks = sm + BK_OFF;
    float* bzs = sm + BZ_OFF;

    const int tid  = threadIdx.x;
    const int w    = tid >> 5;
    const int lane = tid & 31;
    const int g    = lane >> 2;
    const int tig  = lane & 3;
    const size_t row0 = (size_t)blockIdx.x * 64;

    // Stage x tile (64x64) -> xs (row stride 68), coalesced LDG.128/STS.128.
    {
        const float4* xg = (const float4*)(x + row0 * DD);
#pragma unroll
        for (int it = 0; it < 8; it++) {
            int idx = tid + 128 * it;           // float4 index, 0..1023
            int r = idx >> 4, c = (idx & 15) << 2;
            *(float4*)(xs + r * 68 + c) = xg[idx];
        }
    }
    // Stage W (both matrices, tf32-rounded once).
    {
        const float4* wk4 = (const float4*)WxK;
        const float4* wz4 = (const float4*)Wxz;
#pragma unroll
        for (int it = 0; it < 16; it++) {
            int idx = tid + 128 * it;           // float4 index, 0..2047
            int r = idx >> 4, c = (idx & 15) << 2;
            float4 a = wk4[idx], b = wz4[idx];
            float4 at, bt;
            at.x = __uint_as_float(to_tf32(a.x));
            at.y = __uint_as_float(to_tf32(a.y));
            at.z = __uint_as_float(to_tf32(a.z));
            at.w = __uint_as_float(to_tf32(a.w));
            bt.x = __uint_as_float(to_tf32(b.x));
            bt.y = __uint_as_float(to_tf32(b.y));
            bt.z = __uint_as_float(to_tf32(b.z));
            bt.w = __uint_as_float(to_tf32(b.w));
            *(float4*)(wks + r * 68 + c) = at;
            *(float4*)(wzs + r * 68 + c) = bt;
        }
    }
    bks[tid & 127] = bxK[tid & 127];
    bzs[tid & 127] = bxz[tid & 127];
    __syncthreads();

    // A fragments for this warp's 16 rows (tf32-rn), 8 k-chunks.
    uint32_t A[8][4];
    const int rA0 = 16 * w + g, rA1 = rA0 + 8;
#pragma unroll
    for (int kc = 0; kc < 8; kc++) {
        int cb = 8 * kc + tig;
        A[kc][0] = to_tf32(xs[rA0 * 68 + cb]);
        A[kc][1] = to_tf32(xs[rA1 * 68 + cb]);
        A[kc][2] = to_tf32(xs[rA0 * 68 + cb + 4]);
        A[kc][3] = to_tf32(xs[rA1 * 68 + cb + 4]);
    }

    float4* ogz = (float4*)g_gz;     // one float4 = h pair (h, h+1)
    const size_t o0 = (row0 + rA0) * 64;
    const size_t o1 = (row0 + rA1) * 64;

#pragma unroll 4
    for (int nt = 0; nt < 16; nt++) {
        // Prefetch all B fragments for both gates (32 conflict-free LDS.32).
        const float* wkr = wks + (8 * nt + g) * 68 + tig;
        const float* wzr = wzs + (8 * nt + g) * 68 + tig;
        uint32_t BK0[8], BK1[8], BZ0[8], BZ1[8];
#pragma unroll
        for (int kc = 0; kc < 8; kc++) {
            BK0[kc] = __float_as_uint(wkr[8 * kc]);
            BK1[kc] = __float_as_uint(wkr[8 * kc + 4]);
            BZ0[kc] = __float_as_uint(wzr[8 * kc]);
            BZ1[kc] = __float_as_uint(wzr[8 * kc + 4]);
        }
        float cK[4] = {0, 0, 0, 0}, cz[4] = {0, 0, 0, 0};
#pragma unroll
        for (int kc = 0; kc < 8; kc++) {
            mma_tf32(cK, A[kc], BK0[kc], BK1[kc]);
            mma_tf32(cz, A[kc], BZ0[kc], BZ1[kc]);
        }
        const int h0 = 8 * nt + 2 * tig;
        const float bk0 = bks[h0], bk1 = bks[h0 + 1];
        const float bz0 = bzs[h0], bz1 = bzs[h0 + 1];

        float4 v0, v1;
        v0.x = cK[0] + bk0;  v0.y = tanh_hw(cz[0] + bz0);
        v0.z = cK[1] + bk1;  v0.w = tanh_hw(cz[1] + bz1);
        v1.x = cK[2] + bk0;  v1.y = tanh_hw(cz[2] + bz0);
        v1.z = cK[3] + bk1;  v1.w = tanh_hw(cz[3] + bz1);
        ogz[o0 + 4 * nt + tig] = v0;
        ogz[o1 + 4 * nt + tig] = v1;
    }
}

// ---------------------------------------------------------------------------
// Kernel 2: sequential scan (round-11 verbatim; measured 447us).
// 512-thread CTA = GRP(2) batches x 256 threads; per-group named barriers.
// Output i = u>>1 computed by lane pair (u, u^1): half-dots + shfl.bfly.
// ---------------------------------------------------------------------------
__global__ void __launch_bounds__(512, 1)
scan_kernel(const float* __restrict__ WhK, const float* __restrict__ bhK,
            float* __restrict__ out, int dup)
{
    // h[j] stored at j + 8*(j>=64): halves start at 0 and 72 (bank-disjoint).
    __shared__ __align__(16) float hst[2][GRP][144];

    const int tid  = threadIdx.x;
    const int g    = tid >> 8;        // batch group 0..GRP-1
    const int u    = tid & 255;       // thread index within group
    const int i    = u >> 1;          // output index 0..127
    const int half = u & 1;           // which 64-input half
    const int b    = blockIdx.x * GRP + g;

    // This lane's 64 weights: W_hK[i][64*half .. +64) as 32 f32x2.
    ull w[32];
    {
        const ull* wr = (const ull*)(WhK + i * HH + half * 64);
#pragma unroll
        for (int m = 0; m < 32; m++) w[m] = wr[m];
    }
    const float bh = bhK[i];

    const float2* gp = g_gz + (size_t)b * TT * HH + i;
    float* op  = out + (size_t)b * TT * HH + i;
    float* op2 = op + BTH;

    float h = 0.0f;
    if (half == 0) hst[0][g][i + ((i & 64) >> 3)] = 0.0f;

    float2 gz0 = gp[0];
    float2 gz1 = gp[HH];
    float2 gz2 = gp[2 * HH];
    gp += 3 * HH;

    asm volatile("bar.sync %0, %1;" :: "r"(g + 1), "r"(256) : "memory");

    int cur = 0;
    for (int t = 0; t < TT; t++) {
        // Half-dot: 16 LDS.128 (this half starts at float offset 72*half).
        const ulonglong2* hv = (const ulonglong2*)(hst[cur][g] + 72 * half);
        ull a0 = 0, a1 = 0, a2 = 0, a3 = 0;
#pragma unroll
        for (int m = 0; m < 16; m += 2) {     // 16 ulonglong2 = 64 floats
            ulonglong2 hA = hv[m];
            ulonglong2 hB = hv[m + 1];
            fma2(a0, w[2 * m],     hA.x);
            fma2(a1, w[2 * m + 1], hA.y);
            fma2(a2, w[2 * m + 2], hB.x);
            fma2(a3, w[2 * m + 3], hB.y);
        }
        add2(a0, a2); add2(a1, a3); add2(a0, a1);
        float2 p = unpk(a0);
        float s = p.x + p.y;
        s += __shfl_xor_sync(0xFFFFFFFFu, s, 1);   // combine halves
        s += bh;

        // both lanes compute identical activation
        float kg = sigmoid_hw(gz0.x + s);
        h = tanh_hw(fmaf(kg, gz0.y - h, h));

        // rotate prefetch (unconditional; scratch padded)
        gz0 = gz1;
        gz1 = gz2;
        gz2 = *gp;
        gp += HH;

        if (half == 0) op[0] = h;
        else if (dup)  op2[0] = h;
        op += HH; op2 += HH;

        cur ^= 1;
        if (half == 0) hst[cur][g][i + ((i & 64) >> 3)] = h;
        asm volatile("bar.sync %0, %1;" :: "r"(g + 1), "r"(256) : "memory");
    }
}

// ---------------------------------------------------------------------------
extern "C" void kernel_launch(void* const* d_in, const int* in_sizes, int n_in,
                              void* d_out, int out_size)
{
    const float* x   = (const float*)d_in[0];
    const float* WxK = (const float*)d_in[1];
    const float* bxK = (const float*)d_in[2];
    const float* Wxz = (const float*)d_in[3];
    const float* bxz = (const float*)d_in[4];
    const float* WhK = (const float*)d_in[5];
    const float* bhK = (const float*)d_in[6];
    float* out = (float*)d_out;

    const int proj_smem = PROJ_SMEM_FLOATS * (int)sizeof(float);   // ~88KB
    static int attr_set = 0;
    if (!attr_set) {
        cudaFuncSetAttribute(proj_kernel,
                             cudaFuncAttributeMaxDynamicSharedMemorySize,
                             proj_smem);
        attr_set = 1;
    }

    proj_kernel<<<(int)(BT / 64), 128, proj_smem>>>(x, WxK, bxK, Wxz, bxz);

    const int dup = ((size_t)out_size >= 2 * BTH) ? 1 : 0;
    scan_kernel<<<BB / GRP, 512>>>(WhK, bhK, out, dup);
}